// round 5
// baseline (speedup 1.0000x reference)
#include <cuda_runtime.h>
#include <cuda_bf16.h>
#include <math.h>

#define NNODE 10000
#define FDIM  128
#define NB    2
#define NT    8
#define EMAX  321000
#define BATCH (NNODE * FDIM)

// ---------------- device scratch ----------------
__device__ int   g_e64;
__device__ float g_deg[NNODE];
__device__ float g_dinv[NNODE];
__device__ int   g_counts[NNODE];
__device__ int   g_colptr[NNODE + 1];
__device__ int   g_cursor[NNODE];
__device__ int   g_csr_src[EMAX];
__device__ float g_csr_val[EMAX];
__device__ float g_pnorm[2];
__device__ float g_scores0[NT * NB * NNODE];
__device__ float g_scores1[NB * NNODE];
__device__ __align__(16) float g_pooled0[NT * NB * 16384];
__device__ __align__(16) float g_pooled1[NB * 16384];
__device__ __align__(16) float g_H0A[NB * 16384];
__device__ __align__(16) float g_H0B[NB * 16384];
__device__ __align__(16) float g_H1A[NB * 16384];
__device__ __align__(16) float g_H1B[NB * 16384];
__device__ __align__(16) float g_HT[2 * NB * 16384];   // [layer][b][k][j] transposed W
__device__ __align__(16) float g_tmp[NB * BATCH];
__device__ __align__(16) float g_out0[NB * BATCH];

__device__ __forceinline__ const float* gru_in(int l, int t) {
    if (l == 0) return (t & 1) ? g_H0B : g_H0A;
    return (t & 1) ? g_H1B : g_H1A;
}
__device__ __forceinline__ float* gru_out(int l, int t) {
    if (l == 0) return (t & 1) ? g_H0A : g_H0B;
    return (t & 1) ? g_H1A : g_H1B;
}

__device__ __forceinline__ void read_edge(const void* ei, int e, int E, int& s, int& t) {
    if (g_e64) {
        const long long* p = (const long long*)ei;
        s = (int)p[e]; t = (int)p[E + e];
    } else {
        const int* p = (const int*)ei;
        s = p[e]; t = p[E + e];
    }
}

__device__ __forceinline__ unsigned int fkey(float f) {
    unsigned int b = __float_as_uint(f);
    return (b & 0x80000000u) ? ~b : (b | 0x80000000u);
}

// f32x2 packed FMA helpers
__device__ __forceinline__ unsigned long long pk2(float v) {
    unsigned long long r;
    asm("mov.b64 %0, {%1, %1};" : "=l"(r) : "f"(v));
    return r;
}
__device__ __forceinline__ float2 up2(unsigned long long v) {
    float2 r;
    asm("mov.b64 {%0, %1}, %2;" : "=f"(r.x), "=f"(r.y) : "l"(v));
    return r;
}
#define FFMA2(acc, a, b) asm("fma.rn.f32x2 %0, %1, %2, %0;" : "+l"(acc) : "l"(a), "l"(b))

// ---------------- preprocessing ----------------
__global__ void detect_kernel(const int* ei32, int E) {
    __shared__ int any;
    if (threadIdx.x == 0) any = 0;
    __syncthreads();
    int lim = min(2048, E / 2);
    for (int i = threadIdx.x; i < lim; i += 256)
        if (ei32[2 * i + 1] != 0) any = 1;
    __syncthreads();
    if (threadIdx.x == 0) g_e64 = (any == 0) ? 1 : 0;
}

__global__ void zero_kernel() {
    int i = blockIdx.x * 256 + threadIdx.x;
    if (i < NNODE) { g_deg[i] = 0.f; g_counts[i] = 0; }
}

__global__ void norms_kernel(const float* __restrict__ p) {
    int w = threadIdx.x >> 5, l = threadIdx.x & 31;
    const float* pc = p + w * 128;
    float s = 0.f;
    for (int i = l; i < 128; i += 32) { float v = pc[i]; s += v * v; }
    #pragma unroll
    for (int o = 16; o > 0; o >>= 1) s += __shfl_down_sync(0xffffffffu, s, o);
    if (l == 0) g_pnorm[w] = sqrtf(s);
}

__global__ void deg_kernel(const void* ei, const float* __restrict__ ew, int E) {
    int e = blockIdx.x * 256 + threadIdx.x;
    if (e >= E) return;
    int s, t;
    read_edge(ei, e, E, s, t);
    atomicAdd(&g_deg[t], ew[e]);
    atomicAdd(&g_counts[t], 1);
}

__global__ void dinv_kernel() {
    int i = blockIdx.x * 256 + threadIdx.x;
    if (i < NNODE) g_dinv[i] = rsqrtf(g_deg[i] + 1.0f);  // +1 = self-loop weight
}

__global__ void scan_kernel() {
    __shared__ int part[256];
    int tid = threadIdx.x;
    int start = tid * 40;
    int s = 0;
    for (int j = 0; j < 40; ++j) {
        int idx = start + j;
        if (idx < NNODE) s += g_counts[idx];
    }
    part[tid] = s;
    __syncthreads();
    for (int off = 1; off < 256; off <<= 1) {
        int v = (tid >= off) ? part[tid - off] : 0;
        __syncthreads();
        part[tid] += v;
        __syncthreads();
    }
    int run = part[tid] - s;
    for (int j = 0; j < 40; ++j) {
        int idx = start + j;
        if (idx < NNODE) {
            g_colptr[idx] = run; g_cursor[idx] = run;
            run += g_counts[idx];
        }
    }
    if (tid == 255) g_colptr[NNODE] = part[255];
}

__global__ void fill_kernel(const void* ei, const float* __restrict__ ew, int E) {
    int e = blockIdx.x * 256 + threadIdx.x;
    if (e >= E) return;
    int s, t;
    read_edge(ei, e, E, s, t);
    int pos = atomicAdd(&g_cursor[t], 1);
    g_csr_src[pos] = s;
    g_csr_val[pos] = g_dinv[s] * ew[e];
}

__global__ void hinit_kernel(const float* __restrict__ W0) {
    int idx = blockIdx.x * 256 + threadIdx.x;
    if (idx >= 65536) return;
    int c = idx >> 15;
    int b = (idx >> 14) & 1;
    int ji = idx & 16383;
    int j = ji >> 7, i2 = ji & 127;
    float v = W0[c * 16384 + i2 * 128 + j];      // H[c][b][j][i] = W0[c][i][j]
    float* H = (c == 0) ? g_H0A : g_H1A;
    H[b * 16384 + ji] = v;
}

__global__ void scores0_kernel(const float* __restrict__ x, const float* __restrict__ p0) {
    int wid = (blockIdx.x << 3) + (threadIdx.x >> 5);
    if (wid >= NT * NB * NNODE) return;
    int lane = threadIdx.x & 31;
    int t = wid / (NB * NNODE);
    int rem = wid - t * (NB * NNODE);
    int b = rem / NNODE;
    int n = rem - b * NNODE;
    const float* xr = x + (((size_t)(b * NT + t)) * NNODE + n) * FDIM;
    float4 v = __ldg((const float4*)xr + lane);
    float4 pv = __ldg((const float4*)p0 + lane);
    float s = v.x * pv.x + v.y * pv.y + v.z * pv.z + v.w * pv.w;
    #pragma unroll
    for (int o = 16; o > 0; o >>= 1) s += __shfl_down_sync(0xffffffffu, s, o);
    if (lane == 0) g_scores0[wid] = s / g_pnorm[0];
}

// ---------------- top-k 128 of 10000 + pool ----------------
#define TKCAP 1024
__global__ void __launch_bounds__(1024) topk_pool_kernel(const float* __restrict__ x, int mode) {
    __shared__ int histW[8][256];
    __shared__ unsigned int cKey[TKCAP];
    __shared__ int cIdx[TKCAP];
    __shared__ float cVal[TKCAP];
    __shared__ int sCnt, sSel, sAdd;
    __shared__ int rIdx[128];
    __shared__ float rTanh[128];

    int tid = threadIdx.x;
    int bid = blockIdx.x;
    int grp = tid >> 7;

    const float* sc;
    const float* feat;
    float* pool;
    if (mode == 0) {
        int t = bid >> 1, b = bid & 1;
        sc = g_scores0 + (size_t)bid * NNODE;
        feat = x + ((size_t)(b * NT + t)) * BATCH;
        pool = g_pooled0 + (size_t)bid * 16384;
    } else {
        int b = bid;
        sc = g_scores1 + (size_t)b * NNODE;
        feat = g_out0 + (size_t)b * BATCH;
        pool = g_pooled1 + (size_t)b * 16384;
    }

    unsigned int prefix = 0, pmask = 0;
    int K = 128;
    for (int shift = 24; shift >= 0; shift -= 8) {
        for (int i = tid; i < 8 * 256; i += 1024) ((int*)histW)[i] = 0;
        __syncthreads();
        for (int n = tid; n < NNODE; n += 1024) {
            unsigned int kk = fkey(sc[n]);
            if ((kk & pmask) == prefix) atomicAdd(&histW[grp][(kk >> shift) & 255], 1);
        }
        __syncthreads();
        if (tid < 256) {
            int s = 0;
            #pragma unroll
            for (int g = 0; g < 8; ++g) s += histW[g][tid];
            histW[0][tid] = s;
        }
        __syncthreads();
        if (tid == 0) {
            int cum = 0, bsel = 0;
            for (int bkt = 255; bkt >= 0; --bkt) {
                int h = histW[0][bkt];
                if (cum + h >= K) { bsel = bkt; break; }
                cum += h;
            }
            sSel = bsel; sAdd = cum;
        }
        __syncthreads();
        prefix |= ((unsigned int)sSel) << shift;
        pmask |= 0xFFu << shift;
        K -= sAdd;
        __syncthreads();
    }
    if (tid == 0) sCnt = 0;
    __syncthreads();
    for (int n = tid; n < NNODE; n += 1024) {
        float v = sc[n];
        unsigned int kk = fkey(v);
        if (kk >= prefix) {
            int pos = atomicAdd(&sCnt, 1);
            if (pos < TKCAP) { cKey[pos] = kk; cIdx[pos] = n; cVal[pos] = v; }
        }
    }
    __syncthreads();
    int C = min(sCnt, TKCAP);
    for (int i = tid; i < C; i += 1024) {
        unsigned int ki = cKey[i];
        int ii = cIdx[i];
        int rank = 0;
        for (int j = 0; j < C; ++j) {
            unsigned int kj = cKey[j];
            rank += (kj > ki) || (kj == ki && cIdx[j] < ii);
        }
        if (rank < 128) { rIdx[rank] = ii; rTanh[rank] = tanhf(cVal[i]); }
    }
    __syncthreads();
    for (int i = tid; i < 4096; i += 1024) {   // 128 rows x 32 float4
        int row = i >> 5, q = i & 31;
        float4 v = __ldg((const float4*)(feat + (size_t)rIdx[row] * FDIM) + q);
        float s = rTanh[row];
        v.x *= s; v.y *= s; v.z *= s; v.w *= s;
        *((float4*)(pool + row * 128) + q) = v;
    }
}

// ---------------- fused GRU ----------------
__global__ void __launch_bounds__(256) gru_kernel(int layer, int t,
                                                  const float* __restrict__ w_ih,
                                                  const float* __restrict__ w_hh,
                                                  const float* __restrict__ b_ih,
                                                  const float* __restrict__ b_hh) {
    __shared__ float xs[16][33], hs[16][33];
    __shared__ float wi[3][16][33], wh[3][16][33];
    const float* xg = (layer == 0) ? (g_pooled0 + (size_t)t * 32768) : g_pooled1;
    const float* Hin = gru_in(layer, t);
    float* Hout = gru_out(layer, t);

    int tid = threadIdx.x;
    int r0 = blockIdx.x * 16;
    int h0 = blockIdx.y * 16;
    int hh = tid & 15, rr = tid >> 4;
    float acc[6] = {0.f, 0.f, 0.f, 0.f, 0.f, 0.f};

    for (int kc = 0; kc < 128; kc += 32) {
        for (int i = tid; i < 512; i += 256) {
            int r = i >> 5, k = i & 31;
            xs[r][k] = xg[(r0 + r) * 128 + kc + k];
            hs[r][k] = Hin[(r0 + r) * 128 + kc + k];
        }
        #pragma unroll
        for (int g = 0; g < 3; ++g)
            for (int i = tid; i < 512; i += 256) {
                int r = i >> 5, k = i & 31;
                wi[g][r][k] = w_ih[(g * 128 + h0 + r) * 128 + kc + k];
                wh[g][r][k] = w_hh[(g * 128 + h0 + r) * 128 + kc + k];
            }
        __syncthreads();
        #pragma unroll
        for (int k = 0; k < 32; ++k) {
            float xv = xs[rr][k], hv = hs[rr][k];
            acc[0] = fmaf(xv, wi[0][hh][k], acc[0]);
            acc[1] = fmaf(xv, wi[1][hh][k], acc[1]);
            acc[2] = fmaf(xv, wi[2][hh][k], acc[2]);
            acc[3] = fmaf(hv, wh[0][hh][k], acc[3]);
            acc[4] = fmaf(hv, wh[1][hh][k], acc[4]);
            acc[5] = fmaf(hv, wh[2][hh][k], acc[5]);
        }
        __syncthreads();
    }
    int row = r0 + rr, h = h0 + hh;
    float gir = acc[0] + b_ih[h], giz = acc[1] + b_ih[128 + h], gin = acc[2] + b_ih[256 + h];
    float ghr = acc[3] + b_hh[h], ghz = acc[4] + b_hh[128 + h], ghn = acc[5] + b_hh[256 + h];
    float r = 1.f / (1.f + expf(-(gir + ghr)));
    float z = 1.f / (1.f + expf(-(giz + ghz)));
    float n = tanhf(fmaf(r, ghn, gin));
    float hv = (1.f - z) * n + z * Hin[row * 128 + h];
    Hout[row * 128 + h] = hv;
    int b = row >> 7, j = row & 127;
    g_HT[(size_t)(layer * 2 + b) * 16384 + h * 128 + j] = hv;  // transposed for GEMM
}

// ---------------- GEMM: C[b,n,j] = sum_k A[b,n,k] * HT[b,k,j] ----------------
#define GEMM_SMEM ((64 * 128 + 128 * 132) * 4)
__global__ void __launch_bounds__(256, 2) gemm_kernel(const float* __restrict__ x, int mode, int t) {
    extern __shared__ float sm[];
    float* As = sm;             // [64][128]
    float* Hs = sm + 64 * 128;  // [128][132]
    int b = blockIdx.y;
    const float* A = (mode == 0)
        ? (x + ((size_t)(b * NT + t)) * BATCH)
        : (g_out0 + (size_t)b * BATCH);
    const float* HT = g_HT + (size_t)(mode * 2 + b) * 16384;
    float* C = g_tmp + (size_t)b * BATCH;

    int tid = threadIdx.x;
    int rowBase = blockIdx.x * 64;

    for (int i = tid; i < 16384; i += 256) {
        int k = i >> 7, j = i & 127;
        Hs[k * 132 + j] = HT[i];
    }
    for (int i = tid; i < 2048; i += 256) {
        int r = i >> 5, c4 = i & 31;
        int row = rowBase + r;
        float4 v = (row < NNODE) ? __ldg((const float4*)(A + (size_t)row * 128) + c4)
                                 : make_float4(0.f, 0.f, 0.f, 0.f);
        *((float4*)(As + r * 128) + c4) = v;
    }
    __syncthreads();

    int c0 = (tid & 15) * 4;      // cols c0..c0+3 and c0+64..c0+67
    int r0 = (tid >> 4) * 4;
    unsigned long long aA[4][2], aB[4][2];
    #pragma unroll
    for (int i = 0; i < 4; ++i) { aA[i][0] = aA[i][1] = aB[i][0] = aB[i][1] = 0ull; }

    const float* ar = As + r0 * 128;
    #pragma unroll 4
    for (int k = 0; k < 128; ++k) {
        ulonglong2 hA = *(const ulonglong2*)(Hs + k * 132 + c0);
        ulonglong2 hB = *(const ulonglong2*)(Hs + k * 132 + c0 + 64);
        #pragma unroll
        for (int i = 0; i < 4; ++i) {
            unsigned long long ap = pk2(ar[i * 128 + k]);
            FFMA2(aA[i][0], ap, hA.x);
            FFMA2(aA[i][1], ap, hA.y);
            FFMA2(aB[i][0], ap, hB.x);
            FFMA2(aB[i][1], ap, hB.y);
        }
    }
    #pragma unroll
    for (int i = 0; i < 4; ++i) {
        int row = rowBase + r0 + i;
        if (row < NNODE) {
            float2 l0 = up2(aA[i][0]), l1 = up2(aA[i][1]);
            float2 m0 = up2(aB[i][0]), m1 = up2(aB[i][1]);
            *((float4*)(C + (size_t)row * 128 + c0)) = make_float4(l0.x, l0.y, l1.x, l1.y);
            *((float4*)(C + (size_t)row * 128 + c0 + 64)) = make_float4(m0.x, m0.y, m1.x, m1.y);
        }
    }
}

// ---------------- propagation + bias + relu (+ fused layer-1 scores) ----------------
__global__ void __launch_bounds__(64) prop_kernel(int writeFinal, float* __restrict__ dout,
                                                  const float* __restrict__ p1,
                                                  const float* __restrict__ biasc) {
    __shared__ int sSrc[64];
    __shared__ float sVal[64];
    int i = blockIdx.x;
    int tid = threadIdx.x;
    int b = tid >> 5, q = tid & 31;
    const float* tb = g_tmp + (size_t)b * BATCH;
    int e0 = g_colptr[i], e1 = g_colptr[i + 1];
    float4 acc = make_float4(0.f, 0.f, 0.f, 0.f);

    for (int base = e0; base < e1; base += 64) {
        int m = min(64, e1 - base);
        if (tid < m) { sSrc[tid] = g_csr_src[base + tid]; sVal[tid] = g_csr_val[base + tid]; }
        __syncthreads();
        #pragma unroll 2
        for (int e = 0; e < m; ++e) {
            int s = sSrc[e];
            float v = sVal[e];
            float4 r = __ldg((const float4*)(tb + (size_t)s * 128) + q);
            acc.x = fmaf(v, r.x, acc.x); acc.y = fmaf(v, r.y, acc.y);
            acc.z = fmaf(v, r.z, acc.z); acc.w = fmaf(v, r.w, acc.w);
        }
        __syncthreads();
    }
    float di = g_dinv[i];
    float4 sv = __ldg((const float4*)(tb + (size_t)i * 128) + q);
    acc.x = fmaf(di, sv.x, acc.x); acc.y = fmaf(di, sv.y, acc.y);
    acc.z = fmaf(di, sv.z, acc.z); acc.w = fmaf(di, sv.w, acc.w);
    float4 bb = __ldg((const float4*)biasc + q);
    float4 o;
    o.x = fmaxf(fmaf(di, acc.x, bb.x), 0.f);
    o.y = fmaxf(fmaf(di, acc.y, bb.y), 0.f);
    o.z = fmaxf(fmaf(di, acc.z, bb.z), 0.f);
    o.w = fmaxf(fmaf(di, acc.w, bb.w), 0.f);
    float* dst = writeFinal ? (dout + (size_t)b * BATCH + (size_t)i * 128)
                            : (g_out0 + (size_t)b * BATCH + (size_t)i * 128);
    *((float4*)dst + q) = o;
    if (!writeFinal) {
        float4 pv = __ldg((const float4*)p1 + q);
        float s = o.x * pv.x + o.y * pv.y + o.z * pv.z + o.w * pv.w;
        #pragma unroll
        for (int off = 16; off > 0; off >>= 1) s += __shfl_down_sync(0xffffffffu, s, off);
        if (q == 0) g_scores1[b * NNODE + i] = s / g_pnorm[1];
    }
}

// ---------------- launcher ----------------
extern "C" void kernel_launch(void* const* d_in, const int* in_sizes, int n_in,
                              void* d_out, int out_size) {
    const float* x   = (const float*)d_in[0];
    const void*  ei  = d_in[1];
    const float* ew  = (const float*)d_in[2];
    const float* W0  = (const float*)d_in[3];
    const float* p   = (const float*)d_in[4];
    const float* wih = (const float*)d_in[5];
    const float* whh = (const float*)d_in[6];
    const float* bih = (const float*)d_in[7];
    const float* bhh = (const float*)d_in[8];
    const float* bias = (const float*)d_in[9];
    float* dout = (float*)d_out;
    int E = in_sizes[2];

    cudaFuncSetAttribute(gemm_kernel, cudaFuncAttributeMaxDynamicSharedMemorySize, GEMM_SMEM);

    detect_kernel<<<1, 256>>>((const int*)ei, E);
    zero_kernel<<<(NNODE + 255) / 256, 256>>>();
    norms_kernel<<<1, 64>>>(p);
    deg_kernel<<<(E + 255) / 256, 256>>>(ei, ew, E);
    dinv_kernel<<<(NNODE + 255) / 256, 256>>>();
    scan_kernel<<<1, 256>>>();
    fill_kernel<<<(E + 255) / 256, 256>>>(ei, ew, E);
    hinit_kernel<<<256, 256>>>(W0);
    // FIX (R4): 8 warps per 256-thread block -> one block covers 8 scores,
    // grid must be ceil(160000/8) = 20000, not ceil(160000/2048).
    scores0_kernel<<<(NT * NB * NNODE + 7) / 8, 256>>>(x, p);
    topk_pool_kernel<<<16, 1024>>>(x, 0);

    dim3 gruGrid(16, 8);
    dim3 gemmGrid((NNODE + 63) / 64, NB);
    for (int t = 0; t < 8; ++t) {
        gru_kernel<<<gruGrid, 256>>>(0, t, wih, whh, bih, bhh);
        gemm_kernel<<<gemmGrid, 256, GEMM_SMEM>>>(x, 0, t);
        prop_kernel<<<NNODE, 64>>>(0, dout, p + 128, bias);
        topk_pool_kernel<<<2, 1024>>>(x, 1);
        gru_kernel<<<gruGrid, 256>>>(1, t, wih + 49152, whh + 49152, bih + 384, bhh + 384);
    }
    gemm_kernel<<<gemmGrid, 256, GEMM_SMEM>>>(x, 1, 7);
    prop_kernel<<<NNODE, 64>>>(1, dout, p + 128, bias + 128);
}

// round 6
// speedup vs baseline: 1.4369x; 1.4369x over previous
#include <cuda_runtime.h>
#include <cuda_bf16.h>
#include <math.h>

#define NNODE 10000
#define FDIM  128
#define NB    2
#define NT    8
#define EMAX  321000
#define BATCH (NNODE * FDIM)

// ---------------- device scratch ----------------
__device__ int   g_e64;
__device__ float g_deg[NNODE];
__device__ float g_dinv[NNODE];
__device__ int   g_counts[NNODE];
__device__ int   g_colptr[NNODE + 1];
__device__ int   g_cursor[NNODE];
__device__ int2  g_csr[EMAX];                 // {src, val bits}
__device__ float g_pnorm[2];
__device__ float g_scores0[NT * NB * NNODE];
__device__ float g_scores1All[NT * NB * NNODE];
__device__ __align__(16) float g_pooled0[NT * NB * 16384];
__device__ __align__(16) float g_pooled1All[NT * NB * 16384];
__device__ __align__(16) float g_H0A[NB * 16384];
__device__ __align__(16) float g_H0B[NB * 16384];
__device__ __align__(16) float g_H1A[NB * 16384];
__device__ __align__(16) float g_H1B[NB * 16384];
__device__ __align__(16) float g_HT0All[NT * NB * 16384];  // [t][b][k][j]
__device__ __align__(16) float g_HT1[NB * 16384];
__device__ __align__(16) float g_tmpAll[NT * NB * BATCH];  // 82 MB
__device__ __align__(16) float g_out0All[NT * NB * BATCH]; // 82 MB

__device__ __forceinline__ void read_edge(const void* ei, int e, int E, int& s, int& t) {
    if (g_e64) {
        const long long* p = (const long long*)ei;
        s = (int)p[e]; t = (int)p[E + e];
    } else {
        const int* p = (const int*)ei;
        s = p[e]; t = p[E + e];
    }
}

__device__ __forceinline__ unsigned int fkey(float f) {
    unsigned int b = __float_as_uint(f);
    return (b & 0x80000000u) ? ~b : (b | 0x80000000u);
}

// f32x2 packed FMA helpers
__device__ __forceinline__ unsigned long long pk2(float v) {
    unsigned long long r;
    asm("mov.b64 %0, {%1, %1};" : "=l"(r) : "f"(v));
    return r;
}
__device__ __forceinline__ float2 up2(unsigned long long v) {
    float2 r;
    asm("mov.b64 {%0, %1}, %2;" : "=f"(r.x), "=f"(r.y) : "l"(v));
    return r;
}
#define FFMA2(acc, a, b) asm("fma.rn.f32x2 %0, %1, %2, %0;" : "+l"(acc) : "l"(a), "l"(b))

// ---------------- preprocessing ----------------
__global__ void detect_kernel(const int* ei32, int E) {
    __shared__ int any;
    if (threadIdx.x == 0) any = 0;
    __syncthreads();
    int lim = min(2048, E / 2);
    for (int i = threadIdx.x; i < lim; i += 256)
        if (ei32[2 * i + 1] != 0) any = 1;
    __syncthreads();
    if (threadIdx.x == 0) g_e64 = (any == 0) ? 1 : 0;
}

__global__ void zero_kernel() {
    int i = blockIdx.x * 256 + threadIdx.x;
    if (i < NNODE) { g_deg[i] = 0.f; g_counts[i] = 0; }
}

__global__ void norms_kernel(const float* __restrict__ p) {
    int w = threadIdx.x >> 5, l = threadIdx.x & 31;
    const float* pc = p + w * 128;
    float s = 0.f;
    for (int i = l; i < 128; i += 32) { float v = pc[i]; s += v * v; }
    #pragma unroll
    for (int o = 16; o > 0; o >>= 1) s += __shfl_down_sync(0xffffffffu, s, o);
    if (l == 0) g_pnorm[w] = sqrtf(s);
}

__global__ void deg_kernel(const void* ei, const float* __restrict__ ew, int E) {
    int e = blockIdx.x * 256 + threadIdx.x;
    if (e >= E) return;
    int s, t;
    read_edge(ei, e, E, s, t);
    atomicAdd(&g_deg[t], ew[e]);
    atomicAdd(&g_counts[t], 1);
}

__global__ void dinv_kernel() {
    int i = blockIdx.x * 256 + threadIdx.x;
    if (i < NNODE) g_dinv[i] = rsqrtf(g_deg[i] + 1.0f);  // +1 = self-loop weight
}

__global__ void scan_kernel() {
    __shared__ int part[256];
    int tid = threadIdx.x;
    int start = tid * 40;
    int s = 0;
    for (int j = 0; j < 40; ++j) {
        int idx = start + j;
        if (idx < NNODE) s += g_counts[idx];
    }
    part[tid] = s;
    __syncthreads();
    for (int off = 1; off < 256; off <<= 1) {
        int v = (tid >= off) ? part[tid - off] : 0;
        __syncthreads();
        part[tid] += v;
        __syncthreads();
    }
    int run = part[tid] - s;
    for (int j = 0; j < 40; ++j) {
        int idx = start + j;
        if (idx < NNODE) {
            g_colptr[idx] = run; g_cursor[idx] = run;
            run += g_counts[idx];
        }
    }
    if (tid == 255) g_colptr[NNODE] = part[255];
}

__global__ void fill_kernel(const void* ei, const float* __restrict__ ew, int E) {
    int e = blockIdx.x * 256 + threadIdx.x;
    if (e >= E) return;
    int s, t;
    read_edge(ei, e, E, s, t);
    int pos = atomicAdd(&g_cursor[t], 1);
    g_csr[pos] = make_int2(s, __float_as_int(g_dinv[s] * ew[e]));
}

__global__ void hinit_kernel(const float* __restrict__ W0) {
    int idx = blockIdx.x * 256 + threadIdx.x;
    if (idx >= 65536) return;
    int c = idx >> 15;
    int b = (idx >> 14) & 1;
    int ji = idx & 16383;
    int j = ji >> 7, i2 = ji & 127;
    float v = W0[c * 16384 + i2 * 128 + j];      // H[c][b][j][i] = W0[c][i][j]
    float* H = (c == 0) ? g_H0A : g_H1A;
    H[b * 16384 + ji] = v;
}

__global__ void scores0_kernel(const float* __restrict__ x, const float* __restrict__ p0) {
    int wid = (blockIdx.x << 3) + (threadIdx.x >> 5);
    if (wid >= NT * NB * NNODE) return;
    int lane = threadIdx.x & 31;
    int t = wid / (NB * NNODE);
    int rem = wid - t * (NB * NNODE);
    int b = rem / NNODE;
    int n = rem - b * NNODE;
    const float* xr = x + (((size_t)(b * NT + t)) * NNODE + n) * FDIM;
    float4 v = __ldg((const float4*)xr + lane);
    float4 pv = __ldg((const float4*)p0 + lane);
    float s = v.x * pv.x + v.y * pv.y + v.z * pv.z + v.w * pv.w;
    #pragma unroll
    for (int o = 16; o > 0; o >>= 1) s += __shfl_down_sync(0xffffffffu, s, o);
    if (lane == 0) g_scores0[wid] = s / g_pnorm[0];
}

// ---------------- top-k 128 of 10000 + pool (16 blocks, both modes) ----------------
#define TKCAP 1024
__global__ void __launch_bounds__(1024) topk_pool_kernel(const float* __restrict__ x, int mode) {
    __shared__ int histW[8][256];
    __shared__ unsigned int cKey[TKCAP];
    __shared__ int cIdx[TKCAP];
    __shared__ float cVal[TKCAP];
    __shared__ int sCnt, sSel, sAdd;
    __shared__ int rIdx[128];
    __shared__ float rTanh[128];

    int tid = threadIdx.x;
    int bid = blockIdx.x;      // = t*2 + b
    int grp = tid >> 7;

    const float* sc;
    const float* feat;
    float* pool;
    if (mode == 0) {
        int t = bid >> 1, b = bid & 1;
        sc = g_scores0 + (size_t)bid * NNODE;
        feat = x + ((size_t)(b * NT + t)) * BATCH;
        pool = g_pooled0 + (size_t)bid * 16384;
    } else {
        sc = g_scores1All + (size_t)bid * NNODE;
        feat = g_out0All + (size_t)bid * BATCH;
        pool = g_pooled1All + (size_t)bid * 16384;
    }

    unsigned int prefix = 0, pmask = 0;
    int K = 128;
    for (int shift = 24; shift >= 0; shift -= 8) {
        for (int i = tid; i < 8 * 256; i += 1024) ((int*)histW)[i] = 0;
        __syncthreads();
        for (int n = tid; n < NNODE; n += 1024) {
            unsigned int kk = fkey(sc[n]);
            if ((kk & pmask) == prefix) atomicAdd(&histW[grp][(kk >> shift) & 255], 1);
        }
        __syncthreads();
        if (tid < 256) {
            int s = 0;
            #pragma unroll
            for (int g = 0; g < 8; ++g) s += histW[g][tid];
            histW[0][tid] = s;
        }
        __syncthreads();
        if (tid == 0) {
            int cum = 0, bsel = 0;
            for (int bkt = 255; bkt >= 0; --bkt) {
                int h = histW[0][bkt];
                if (cum + h >= K) { bsel = bkt; break; }
                cum += h;
            }
            sSel = bsel; sAdd = cum;
        }
        __syncthreads();
        prefix |= ((unsigned int)sSel) << shift;
        pmask |= 0xFFu << shift;
        K -= sAdd;
        __syncthreads();
    }
    if (tid == 0) sCnt = 0;
    __syncthreads();
    for (int n = tid; n < NNODE; n += 1024) {
        float v = sc[n];
        unsigned int kk = fkey(v);
        if (kk >= prefix) {
            int pos = atomicAdd(&sCnt, 1);
            if (pos < TKCAP) { cKey[pos] = kk; cIdx[pos] = n; cVal[pos] = v; }
        }
    }
    __syncthreads();
    int C = min(sCnt, TKCAP);
    for (int i = tid; i < C; i += 1024) {
        unsigned int ki = cKey[i];
        int ii = cIdx[i];
        int rank = 0;
        for (int j = 0; j < C; ++j) {
            unsigned int kj = cKey[j];
            rank += (kj > ki) || (kj == ki && cIdx[j] < ii);
        }
        if (rank < 128) { rIdx[rank] = ii; rTanh[rank] = tanhf(cVal[i]); }
    }
    __syncthreads();
    for (int i = tid; i < 4096; i += 1024) {
        int row = i >> 5, q = i & 31;
        float4 v = __ldg((const float4*)(feat + (size_t)rIdx[row] * FDIM) + q);
        float s = rTanh[row];
        v.x *= s; v.y *= s; v.z *= s; v.w *= s;
        *((float4*)(pool + row * 128) + q) = v;
    }
}

// ---------------- fused GRU (pointer-parameterized) ----------------
__global__ void __launch_bounds__(256) gru_kernel(const float* __restrict__ xg,
                                                  const float* __restrict__ Hin,
                                                  float* __restrict__ Hout,
                                                  float* __restrict__ HTdst,
                                                  const float* __restrict__ w_ih,
                                                  const float* __restrict__ w_hh,
                                                  const float* __restrict__ b_ih,
                                                  const float* __restrict__ b_hh) {
    __shared__ float xs[16][33], hs[16][33];
    __shared__ float wi[3][16][33], wh[3][16][33];
    int tid = threadIdx.x;
    int r0 = blockIdx.x * 16;
    int h0 = blockIdx.y * 16;
    int hh = tid & 15, rr = tid >> 4;
    float acc[6] = {0.f, 0.f, 0.f, 0.f, 0.f, 0.f};

    for (int kc = 0; kc < 128; kc += 32) {
        for (int i = tid; i < 512; i += 256) {
            int r = i >> 5, k = i & 31;
            xs[r][k] = xg[(r0 + r) * 128 + kc + k];
            hs[r][k] = Hin[(r0 + r) * 128 + kc + k];
        }
        #pragma unroll
        for (int g = 0; g < 3; ++g)
            for (int i = tid; i < 512; i += 256) {
                int r = i >> 5, k = i & 31;
                wi[g][r][k] = w_ih[(g * 128 + h0 + r) * 128 + kc + k];
                wh[g][r][k] = w_hh[(g * 128 + h0 + r) * 128 + kc + k];
            }
        __syncthreads();
        #pragma unroll
        for (int k = 0; k < 32; ++k) {
            float xv = xs[rr][k], hv = hs[rr][k];
            acc[0] = fmaf(xv, wi[0][hh][k], acc[0]);
            acc[1] = fmaf(xv, wi[1][hh][k], acc[1]);
            acc[2] = fmaf(xv, wi[2][hh][k], acc[2]);
            acc[3] = fmaf(hv, wh[0][hh][k], acc[3]);
            acc[4] = fmaf(hv, wh[1][hh][k], acc[4]);
            acc[5] = fmaf(hv, wh[2][hh][k], acc[5]);
        }
        __syncthreads();
    }
    int row = r0 + rr, h = h0 + hh;
    float gir = acc[0] + b_ih[h], giz = acc[1] + b_ih[128 + h], gin = acc[2] + b_ih[256 + h];
    float ghr = acc[3] + b_hh[h], ghz = acc[4] + b_hh[128 + h], ghn = acc[5] + b_hh[256 + h];
    float r = 1.f / (1.f + expf(-(gir + ghr)));
    float z = 1.f / (1.f + expf(-(giz + ghz)));
    float n = tanhf(fmaf(r, ghn, gin));
    float hv = (1.f - z) * n + z * Hin[row * 128 + h];
    Hout[row * 128 + h] = hv;
    int b = row >> 7, j = row & 127;
    HTdst[(size_t)b * 16384 + h * 128 + j] = hv;   // transposed for GEMM
}

// ---------------- GEMM: C[idx,n,j] = sum_k A[n,k] * HT[idx,k,j] ----------------
#define GEMM_SMEM ((64 * 128 + 128 * 132) * 4)
__global__ void __launch_bounds__(256, 2) gemm_kernel(const float* __restrict__ A,
                                                      long sy, long sz,
                                                      const float* __restrict__ HT,
                                                      float* __restrict__ C) {
    extern __shared__ float sm[];
    float* As = sm;             // [64][128]
    float* Hs = sm + 64 * 128;  // [128][132]
    int idx = blockIdx.z * gridDim.y + blockIdx.y;
    const float* Ab = A + (size_t)blockIdx.y * sy + (size_t)blockIdx.z * sz;
    const float* HTb = HT + (size_t)idx * 16384;
    float* Cb = C + (size_t)idx * BATCH;

    int tid = threadIdx.x;
    int rowBase = blockIdx.x * 64;

    for (int i = tid; i < 16384; i += 256) {
        int k = i >> 7, j = i & 127;
        Hs[k * 132 + j] = HTb[i];
    }
    for (int i = tid; i < 2048; i += 256) {
        int r = i >> 5, c4 = i & 31;
        int row = rowBase + r;
        float4 v = (row < NNODE) ? __ldg((const float4*)(Ab + (size_t)row * 128) + c4)
                                 : make_float4(0.f, 0.f, 0.f, 0.f);
        *((float4*)(As + r * 128) + c4) = v;
    }
    __syncthreads();

    int c0 = (tid & 15) * 4;
    int r0 = (tid >> 4) * 4;
    unsigned long long aA[4][2], aB[4][2];
    #pragma unroll
    for (int i = 0; i < 4; ++i) { aA[i][0] = aA[i][1] = aB[i][0] = aB[i][1] = 0ull; }

    const float* ar = As + r0 * 128;
    #pragma unroll 4
    for (int k = 0; k < 128; ++k) {
        ulonglong2 hA = *(const ulonglong2*)(Hs + k * 132 + c0);
        ulonglong2 hB = *(const ulonglong2*)(Hs + k * 132 + c0 + 64);
        #pragma unroll
        for (int i = 0; i < 4; ++i) {
            unsigned long long ap = pk2(ar[i * 128 + k]);
            FFMA2(aA[i][0], ap, hA.x);
            FFMA2(aA[i][1], ap, hA.y);
            FFMA2(aB[i][0], ap, hB.x);
            FFMA2(aB[i][1], ap, hB.y);
        }
    }
    #pragma unroll
    for (int i = 0; i < 4; ++i) {
        int row = rowBase + r0 + i;
        if (row < NNODE) {
            float2 l0 = up2(aA[i][0]), l1 = up2(aA[i][1]);
            float2 m0 = up2(aB[i][0]), m1 = up2(aB[i][1]);
            *((float4*)(Cb + (size_t)row * 128 + c0)) = make_float4(l0.x, l0.y, l1.x, l1.y);
            *((float4*)(Cb + (size_t)row * 128 + c0 + 64)) = make_float4(m0.x, m0.y, m1.x, m1.y);
        }
    }
}

// ---------------- propagation + bias + relu (+ fused layer-1 scores) ----------------
// grid (NNODE, nT), 128 threads: 2 edge-groups x 2 batches x 32 f4-lanes
__global__ void __launch_bounds__(128) prop_kernel(const float* __restrict__ tmpAll,
                                                   float* __restrict__ outAll,
                                                   float* __restrict__ scAll,
                                                   const float* __restrict__ p1,
                                                   const float* __restrict__ biasc,
                                                   int writeScores) {
    __shared__ float4 sacc[2][32];
    int i = blockIdx.x;
    int ty = blockIdx.y;
    int tid = threadIdx.x;
    int g = tid >> 6, b = (tid >> 5) & 1, q = tid & 31;
    const float* tb = tmpAll + ((size_t)(ty * 2 + b)) * BATCH;
    int e0 = g_colptr[i], e1 = g_colptr[i + 1];
    float4 acc = make_float4(0.f, 0.f, 0.f, 0.f);

    for (int e = e0 + g; e < e1; e += 2) {
        int2 sv = __ldg(&g_csr[e]);
        float v = __int_as_float(sv.y);
        float4 r = __ldg((const float4*)(tb + (size_t)sv.x * 128) + q);
        acc.x = fmaf(v, r.x, acc.x); acc.y = fmaf(v, r.y, acc.y);
        acc.z = fmaf(v, r.z, acc.z); acc.w = fmaf(v, r.w, acc.w);
    }
    if (g == 1) sacc[b][q] = acc;
    __syncthreads();
    if (g == 0) {
        float4 o2 = sacc[b][q];
        acc.x += o2.x; acc.y += o2.y; acc.z += o2.z; acc.w += o2.w;
        float di = g_dinv[i];
        float4 sv = __ldg((const float4*)(tb + (size_t)i * 128) + q);
        acc.x = fmaf(di, sv.x, acc.x); acc.y = fmaf(di, sv.y, acc.y);
        acc.z = fmaf(di, sv.z, acc.z); acc.w = fmaf(di, sv.w, acc.w);
        float4 bb = __ldg((const float4*)biasc + q);
        float4 o;
        o.x = fmaxf(fmaf(di, acc.x, bb.x), 0.f);
        o.y = fmaxf(fmaf(di, acc.y, bb.y), 0.f);
        o.z = fmaxf(fmaf(di, acc.z, bb.z), 0.f);
        o.w = fmaxf(fmaf(di, acc.w, bb.w), 0.f);
        float4* dst = (float4*)(outAll + ((size_t)(ty * 2 + b)) * BATCH + (size_t)i * 128) + q;
        if (writeScores) {
            __stcs(dst, o);   // streaming: don't evict the gather source from L2
            float4 pv = __ldg((const float4*)p1 + q);
            float s = o.x * pv.x + o.y * pv.y + o.z * pv.z + o.w * pv.w;
            #pragma unroll
            for (int off = 16; off > 0; off >>= 1) s += __shfl_down_sync(0xffffffffu, s, off);
            if (q == 0) scAll[(ty * 2 + b) * NNODE + i] = s / g_pnorm[1];
        } else {
            *dst = o;
        }
    }
}

// ---------------- launcher ----------------
extern "C" void kernel_launch(void* const* d_in, const int* in_sizes, int n_in,
                              void* d_out, int out_size) {
    const float* x   = (const float*)d_in[0];
    const void*  ei  = d_in[1];
    const float* ew  = (const float*)d_in[2];
    const float* W0  = (const float*)d_in[3];
    const float* p   = (const float*)d_in[4];
    const float* wih = (const float*)d_in[5];
    const float* whh = (const float*)d_in[6];
    const float* bih = (const float*)d_in[7];
    const float* bhh = (const float*)d_in[8];
    const float* bias = (const float*)d_in[9];
    float* dout = (float*)d_out;
    int E = in_sizes[2];

    cudaFuncSetAttribute(gemm_kernel, cudaFuncAttributeMaxDynamicSharedMemorySize, GEMM_SMEM);

    // pointers to device globals (host side)
    float *pH0A, *pH0B, *pH1A, *pH1B, *pHT0, *pHT1, *pP0, *pP1, *pTmp, *pOut0, *pSc1;
    cudaGetSymbolAddress((void**)&pH0A, g_H0A);
    cudaGetSymbolAddress((void**)&pH0B, g_H0B);
    cudaGetSymbolAddress((void**)&pH1A, g_H1A);
    cudaGetSymbolAddress((void**)&pH1B, g_H1B);
    cudaGetSymbolAddress((void**)&pHT0, g_HT0All);
    cudaGetSymbolAddress((void**)&pHT1, g_HT1);
    cudaGetSymbolAddress((void**)&pP0, g_pooled0);
    cudaGetSymbolAddress((void**)&pP1, g_pooled1All);
    cudaGetSymbolAddress((void**)&pTmp, g_tmpAll);
    cudaGetSymbolAddress((void**)&pOut0, g_out0All);
    cudaGetSymbolAddress((void**)&pSc1, g_scores1All);

    // ---- preprocessing ----
    detect_kernel<<<1, 256>>>((const int*)ei, E);
    zero_kernel<<<(NNODE + 255) / 256, 256>>>();
    norms_kernel<<<1, 64>>>(p);
    deg_kernel<<<(E + 255) / 256, 256>>>(ei, ew, E);
    dinv_kernel<<<(NNODE + 255) / 256, 256>>>();
    scan_kernel<<<1, 256>>>();
    fill_kernel<<<(E + 255) / 256, 256>>>(ei, ew, E);
    hinit_kernel<<<256, 256>>>(W0);
    scores0_kernel<<<(NT * NB * NNODE + 7) / 8, 256>>>(x, p);
    topk_pool_kernel<<<16, 1024>>>(x, 0);

    dim3 gruGrid(16, 8);
    // ---- layer-0 GRU chain (only serial dependency) ----
    for (int t = 0; t < 8; ++t) {
        const float* Hin = (t & 1) ? pH0B : pH0A;
        float* Hout = (t & 1) ? pH0A : pH0B;
        gru_kernel<<<gruGrid, 256>>>(pP0 + (size_t)t * 32768, Hin, Hout,
                                     pHT0 + (size_t)t * NB * 16384, wih, whh, bih, bhh);
    }
    // ---- all 8 layer-0 GEMMs in one launch ----
    gemm_kernel<<<dim3((NNODE + 63) / 64, 2, 8), 256, GEMM_SMEM>>>(
        x, (long)NT * BATCH, (long)BATCH, pHT0, pTmp);
    // ---- all 8 propagations in two launches (L2 working-set chunks of 4 t) ----
    prop_kernel<<<dim3(NNODE, 4), 128>>>(pTmp, pOut0, pSc1, p + 128, bias, 1);
    prop_kernel<<<dim3(NNODE, 4), 128>>>(pTmp + (size_t)8 * BATCH, pOut0 + (size_t)8 * BATCH,
                                         pSc1 + 8 * NNODE, p + 128, bias, 1);
    // ---- all 8 layer-1 top-k+pool in one launch ----
    topk_pool_kernel<<<16, 1024>>>(x, 1);
    // ---- layer-1 GRU chain ----
    for (int t = 0; t < 8; ++t) {
        const float* Hin = (t & 1) ? pH1B : pH1A;
        float* Hout = (t & 1) ? pH1A : pH1B;
        gru_kernel<<<gruGrid, 256>>>(pP1 + (size_t)t * 32768, Hin, Hout,
                                     pHT1, wih + 49152, whh + 49152, bih + 384, bhh + 384);
    }
    // ---- final layer-1 GEMM (t=7) + propagation to output ----
    gemm_kernel<<<dim3((NNODE + 63) / 64, 2, 1), 256, GEMM_SMEM>>>(
        pOut0 + (size_t)14 * BATCH, (long)BATCH, 0L, pHT1, pTmp);
    prop_kernel<<<dim3(NNODE, 1), 128>>>(pTmp, dout, nullptr, p + 128, bias + 128, 0);
}

// round 7
// speedup vs baseline: 1.4630x; 1.0181x over previous
#include <cuda_runtime.h>
#include <cuda_bf16.h>
#include <math.h>

#define NNODE 10000
#define FDIM  128
#define NB    2
#define NT    8
#define EMAX  321000
#define BATCH (NNODE * FDIM)

// ---------------- device scratch ----------------
__device__ int   g_e64;
__device__ float g_deg[NNODE];
__device__ float g_dinv[NNODE];
__device__ int   g_counts[NNODE];
__device__ int   g_colptr[NNODE + 1];
__device__ int   g_cursor[NNODE];
__device__ int2  g_csr[EMAX];                 // {src, val bits}
__device__ float g_pnorm[2];
__device__ float g_scores0[NT * NB * NNODE];
__device__ float g_scores1All[NT * NB * NNODE];
__device__ __align__(16) float g_pooled0[NT * NB * 16384];
__device__ __align__(16) float g_pooled1All[NT * NB * 16384];
__device__ __align__(16) float g_H0A[NB * 16384];
__device__ __align__(16) float g_H0B[NB * 16384];
__device__ __align__(16) float g_H1A[NB * 16384];
__device__ __align__(16) float g_H1B[NB * 16384];
__device__ __align__(16) float g_HT0All[NT * NB * 16384];  // [t][b][k][j]
__device__ __align__(16) float g_HT1[NB * 16384];
__device__ __align__(16) float g_tmpAll[NT * NB * BATCH];  // 82 MB
__device__ __align__(16) float g_out0All[NT * NB * BATCH]; // 82 MB

__device__ __forceinline__ void read_edge(const void* ei, int e, int E, int& s, int& t) {
    if (g_e64) {
        const long long* p = (const long long*)ei;
        s = (int)p[e]; t = (int)p[E + e];
    } else {
        const int* p = (const int*)ei;
        s = p[e]; t = p[E + e];
    }
}

__device__ __forceinline__ unsigned int fkey(float f) {
    unsigned int b = __float_as_uint(f);
    return (b & 0x80000000u) ? ~b : (b | 0x80000000u);
}

// f32x2 packed FMA helpers
__device__ __forceinline__ unsigned long long pk2(float v) {
    unsigned long long r;
    asm("mov.b64 %0, {%1, %1};" : "=l"(r) : "f"(v));
    return r;
}
__device__ __forceinline__ float2 up2(unsigned long long v) {
    float2 r;
    asm("mov.b64 {%0, %1}, %2;" : "=f"(r.x), "=f"(r.y) : "l"(v));
    return r;
}
#define FFMA2(acc, a, b) asm("fma.rn.f32x2 %0, %1, %2, %0;" : "+l"(acc) : "l"(a), "l"(b))

// ---------------- preprocessing ----------------
__global__ void detect_kernel(const int* ei32, int E) {
    __shared__ int any;
    if (threadIdx.x == 0) any = 0;
    __syncthreads();
    int lim = min(2048, E / 2);
    for (int i = threadIdx.x; i < lim; i += 256)
        if (ei32[2 * i + 1] != 0) any = 1;
    __syncthreads();
    if (threadIdx.x == 0) g_e64 = (any == 0) ? 1 : 0;
}

__global__ void zero_kernel() {
    int i = blockIdx.x * 256 + threadIdx.x;
    if (i < NNODE) { g_deg[i] = 0.f; g_counts[i] = 0; }
}

__global__ void norms_kernel(const float* __restrict__ p) {
    int w = threadIdx.x >> 5, l = threadIdx.x & 31;
    const float* pc = p + w * 128;
    float s = 0.f;
    for (int i = l; i < 128; i += 32) { float v = pc[i]; s += v * v; }
    #pragma unroll
    for (int o = 16; o > 0; o >>= 1) s += __shfl_down_sync(0xffffffffu, s, o);
    if (l == 0) g_pnorm[w] = sqrtf(s);
}

__global__ void deg_kernel(const void* ei, const float* __restrict__ ew, int E) {
    int e = blockIdx.x * 256 + threadIdx.x;
    if (e >= E) return;
    int s, t;
    read_edge(ei, e, E, s, t);
    atomicAdd(&g_deg[t], ew[e]);
    atomicAdd(&g_counts[t], 1);
}

__global__ void dinv_kernel() {
    int i = blockIdx.x * 256 + threadIdx.x;
    if (i < NNODE) g_dinv[i] = rsqrtf(g_deg[i] + 1.0f);  // +1 = self-loop weight
}

__global__ void scan_kernel() {
    __shared__ int part[256];
    int tid = threadIdx.x;
    int start = tid * 40;
    int s = 0;
    for (int j = 0; j < 40; ++j) {
        int idx = start + j;
        if (idx < NNODE) s += g_counts[idx];
    }
    part[tid] = s;
    __syncthreads();
    for (int off = 1; off < 256; off <<= 1) {
        int v = (tid >= off) ? part[tid - off] : 0;
        __syncthreads();
        part[tid] += v;
        __syncthreads();
    }
    int run = part[tid] - s;
    for (int j = 0; j < 40; ++j) {
        int idx = start + j;
        if (idx < NNODE) {
            g_colptr[idx] = run; g_cursor[idx] = run;
            run += g_counts[idx];
        }
    }
    if (tid == 255) g_colptr[NNODE] = part[255];
}

__global__ void fill_kernel(const void* ei, const float* __restrict__ ew, int E) {
    int e = blockIdx.x * 256 + threadIdx.x;
    if (e >= E) return;
    int s, t;
    read_edge(ei, e, E, s, t);
    int pos = atomicAdd(&g_cursor[t], 1);
    g_csr[pos] = make_int2(s, __float_as_int(g_dinv[s] * ew[e]));
}

__global__ void hinit_kernel(const float* __restrict__ W0) {
    int idx = blockIdx.x * 256 + threadIdx.x;
    if (idx >= 65536) return;
    int c = idx >> 15;
    int b = (idx >> 14) & 1;
    int ji = idx & 16383;
    int j = ji >> 7, i2 = ji & 127;
    float v = W0[c * 16384 + i2 * 128 + j];      // H[c][b][j][i] = W0[c][i][j]
    float* H = (c == 0) ? g_H0A : g_H1A;
    H[b * 16384 + ji] = v;
}

__global__ void scores0_kernel(const float* __restrict__ x, const float* __restrict__ p0) {
    int wid = (blockIdx.x << 3) + (threadIdx.x >> 5);
    if (wid >= NT * NB * NNODE) return;
    int lane = threadIdx.x & 31;
    int t = wid / (NB * NNODE);
    int rem = wid - t * (NB * NNODE);
    int b = rem / NNODE;
    int n = rem - b * NNODE;
    const float* xr = x + (((size_t)(b * NT + t)) * NNODE + n) * FDIM;
    float4 v = __ldg((const float4*)xr + lane);
    float4 pv = __ldg((const float4*)p0 + lane);
    float s = v.x * pv.x + v.y * pv.y + v.z * pv.z + v.w * pv.w;
    #pragma unroll
    for (int o = 16; o > 0; o >>= 1) s += __shfl_down_sync(0xffffffffu, s, o);
    if (lane == 0) g_scores0[wid] = s / g_pnorm[0];
}

// ---------------- top-k 128 of 10000 + pool (16 blocks, both modes) ----------------
#define TKCAP 1024
__global__ void __launch_bounds__(1024) topk_pool_kernel(const float* __restrict__ x, int mode) {
    __shared__ int histW[8][256];
    __shared__ unsigned int cKey[TKCAP];
    __shared__ int cIdx[TKCAP];
    __shared__ float cVal[TKCAP];
    __shared__ int sCnt, sSel, sAdd;
    __shared__ int rIdx[128];
    __shared__ float rTanh[128];

    int tid = threadIdx.x;
    int bid = blockIdx.x;      // = t*2 + b
    int grp = tid >> 7;

    const float* sc;
    const float* feat;
    float* pool;
    if (mode == 0) {
        int t = bid >> 1, b = bid & 1;
        sc = g_scores0 + (size_t)bid * NNODE;
        feat = x + ((size_t)(b * NT + t)) * BATCH;
        pool = g_pooled0 + (size_t)bid * 16384;
    } else {
        sc = g_scores1All + (size_t)bid * NNODE;
        feat = g_out0All + (size_t)bid * BATCH;
        pool = g_pooled1All + (size_t)bid * 16384;
    }

    unsigned int prefix = 0, pmask = 0;
    int K = 128;
    for (int shift = 24; shift >= 0; shift -= 8) {
        for (int i = tid; i < 8 * 256; i += 1024) ((int*)histW)[i] = 0;
        __syncthreads();
        for (int n = tid; n < NNODE; n += 1024) {
            unsigned int kk = fkey(sc[n]);
            if ((kk & pmask) == prefix) atomicAdd(&histW[grp][(kk >> shift) & 255], 1);
        }
        __syncthreads();
        if (tid < 256) {
            int s = 0;
            #pragma unroll
            for (int g = 0; g < 8; ++g) s += histW[g][tid];
            histW[0][tid] = s;
        }
        __syncthreads();
        if (tid == 0) {
            int cum = 0, bsel = 0;
            for (int bkt = 255; bkt >= 0; --bkt) {
                int h = histW[0][bkt];
                if (cum + h >= K) { bsel = bkt; break; }
                cum += h;
            }
            sSel = bsel; sAdd = cum;
        }
        __syncthreads();
        prefix |= ((unsigned int)sSel) << shift;
        pmask |= 0xFFu << shift;
        K -= sAdd;
        __syncthreads();
    }
    if (tid == 0) sCnt = 0;
    __syncthreads();
    for (int n = tid; n < NNODE; n += 1024) {
        float v = sc[n];
        unsigned int kk = fkey(v);
        if (kk >= prefix) {
            int pos = atomicAdd(&sCnt, 1);
            if (pos < TKCAP) { cKey[pos] = kk; cIdx[pos] = n; cVal[pos] = v; }
        }
    }
    __syncthreads();
    int C = min(sCnt, TKCAP);
    for (int i = tid; i < C; i += 1024) {
        unsigned int ki = cKey[i];
        int ii = cIdx[i];
        int rank = 0;
        for (int j = 0; j < C; ++j) {
            unsigned int kj = cKey[j];
            rank += (kj > ki) || (kj == ki && cIdx[j] < ii);
        }
        if (rank < 128) { rIdx[rank] = ii; rTanh[rank] = tanhf(cVal[i]); }
    }
    __syncthreads();
    for (int i = tid; i < 4096; i += 1024) {
        int row = i >> 5, q = i & 31;
        float4 v = __ldg((const float4*)(feat + (size_t)rIdx[row] * FDIM) + q);
        float s = rTanh[row];
        v.x *= s; v.y *= s; v.z *= s; v.w *= s;
        *((float4*)(pool + row * 128) + q) = v;
    }
}

// ---------------- fused GRU (pointer-parameterized) ----------------
__global__ void __launch_bounds__(256) gru_kernel(const float* __restrict__ xg,
                                                  const float* __restrict__ Hin,
                                                  float* __restrict__ Hout,
                                                  float* __restrict__ HTdst,
                                                  const float* __restrict__ w_ih,
                                                  const float* __restrict__ w_hh,
                                                  const float* __restrict__ b_ih,
                                                  const float* __restrict__ b_hh) {
    __shared__ float xs[16][33], hs[16][33];
    __shared__ float wi[3][16][33], wh[3][16][33];
    int tid = threadIdx.x;
    int r0 = blockIdx.x * 16;
    int h0 = blockIdx.y * 16;
    int hh = tid & 15, rr = tid >> 4;
    float acc[6] = {0.f, 0.f, 0.f, 0.f, 0.f, 0.f};

    for (int kc = 0; kc < 128; kc += 32) {
        for (int i = tid; i < 512; i += 256) {
            int r = i >> 5, k = i & 31;
            xs[r][k] = xg[(r0 + r) * 128 + kc + k];
            hs[r][k] = Hin[(r0 + r) * 128 + kc + k];
        }
        #pragma unroll
        for (int g = 0; g < 3; ++g)
            for (int i = tid; i < 512; i += 256) {
                int r = i >> 5, k = i & 31;
                wi[g][r][k] = w_ih[(g * 128 + h0 + r) * 128 + kc + k];
                wh[g][r][k] = w_hh[(g * 128 + h0 + r) * 128 + kc + k];
            }
        __syncthreads();
        #pragma unroll
        for (int k = 0; k < 32; ++k) {
            float xv = xs[rr][k], hv = hs[rr][k];
            acc[0] = fmaf(xv, wi[0][hh][k], acc[0]);
            acc[1] = fmaf(xv, wi[1][hh][k], acc[1]);
            acc[2] = fmaf(xv, wi[2][hh][k], acc[2]);
            acc[3] = fmaf(hv, wh[0][hh][k], acc[3]);
            acc[4] = fmaf(hv, wh[1][hh][k], acc[4]);
            acc[5] = fmaf(hv, wh[2][hh][k], acc[5]);
        }
        __syncthreads();
    }
    int row = r0 + rr, h = h0 + hh;
    float gir = acc[0] + b_ih[h], giz = acc[1] + b_ih[128 + h], gin = acc[2] + b_ih[256 + h];
    float ghr = acc[3] + b_hh[h], ghz = acc[4] + b_hh[128 + h], ghn = acc[5] + b_hh[256 + h];
    float r = 1.f / (1.f + expf(-(gir + ghr)));
    float z = 1.f / (1.f + expf(-(giz + ghz)));
    float n = tanhf(fmaf(r, ghn, gin));
    float hv = (1.f - z) * n + z * Hin[row * 128 + h];
    Hout[row * 128 + h] = hv;
    int b = row >> 7, j = row & 127;
    HTdst[(size_t)b * 16384 + h * 128 + j] = hv;   // transposed for GEMM
}

// ---------------- GEMM: C[idx,n,j] = sum_k A[n,k] * HT[idx,k,j] ----------------
#define GEMM_SMEM ((64 * 128 + 128 * 132) * 4)
__global__ void __launch_bounds__(256, 2) gemm_kernel(const float* __restrict__ A,
                                                      long sy, long sz,
                                                      const float* __restrict__ HT,
                                                      float* __restrict__ C) {
    extern __shared__ float sm[];
    float* As = sm;             // [64][128]
    float* Hs = sm + 64 * 128;  // [128][132]
    int idx = blockIdx.z * gridDim.y + blockIdx.y;
    const float* Ab = A + (size_t)blockIdx.y * sy + (size_t)blockIdx.z * sz;
    const float* HTb = HT + (size_t)idx * 16384;
    float* Cb = C + (size_t)idx * BATCH;

    int tid = threadIdx.x;
    int rowBase = blockIdx.x * 64;

    for (int i = tid; i < 16384; i += 256) {
        int k = i >> 7, j = i & 127;
        Hs[k * 132 + j] = HTb[i];
    }
    for (int i = tid; i < 2048; i += 256) {
        int r = i >> 5, c4 = i & 31;
        int row = rowBase + r;
        float4 v = (row < NNODE) ? __ldg((const float4*)(Ab + (size_t)row * 128) + c4)
                                 : make_float4(0.f, 0.f, 0.f, 0.f);
        *((float4*)(As + r * 128) + c4) = v;
    }
    __syncthreads();

    int c0 = (tid & 15) * 4;
    int r0 = (tid >> 4) * 4;
    unsigned long long aA[4][2], aB[4][2];
    #pragma unroll
    for (int i = 0; i < 4; ++i) { aA[i][0] = aA[i][1] = aB[i][0] = aB[i][1] = 0ull; }

    const float* ar = As + r0 * 128;
    #pragma unroll 4
    for (int k = 0; k < 128; ++k) {
        ulonglong2 hA = *(const ulonglong2*)(Hs + k * 132 + c0);
        ulonglong2 hB = *(const ulonglong2*)(Hs + k * 132 + c0 + 64);
        #pragma unroll
        for (int i = 0; i < 4; ++i) {
            unsigned long long ap = pk2(ar[i * 128 + k]);
            FFMA2(aA[i][0], ap, hA.x);
            FFMA2(aA[i][1], ap, hA.y);
            FFMA2(aB[i][0], ap, hB.x);
            FFMA2(aB[i][1], ap, hB.y);
        }
    }
    #pragma unroll
    for (int i = 0; i < 4; ++i) {
        int row = rowBase + r0 + i;
        if (row < NNODE) {
            float2 l0 = up2(aA[i][0]), l1 = up2(aA[i][1]);
            float2 m0 = up2(aB[i][0]), m1 = up2(aB[i][1]);
            *((float4*)(Cb + (size_t)row * 128 + c0)) = make_float4(l0.x, l0.y, l1.x, l1.y);
            *((float4*)(Cb + (size_t)row * 128 + c0 + 64)) = make_float4(m0.x, m0.y, m1.x, m1.y);
        }
    }
}

// ---------------- propagation for ALL 16 (t,b) in one pass ----------------
// grid (NNODE), 256 threads = 8 warps; warp w handles tb = w and w+8.
__global__ void __launch_bounds__(256) prop16_kernel(const float* __restrict__ tmpAll,
                                                     float* __restrict__ outAll,
                                                     float* __restrict__ scAll,
                                                     const float* __restrict__ p1,
                                                     const float* __restrict__ biasc) {
    __shared__ int2 se[256];
    int i = blockIdx.x;
    int tid = threadIdx.x;
    int w = tid >> 5, q = tid & 31;
    int e0 = g_colptr[i], e1 = g_colptr[i + 1];
    const float* tb0 = tmpAll + (size_t)w * BATCH;
    const float* tb1 = tmpAll + (size_t)(w + 8) * BATCH;
    float4 a0 = make_float4(0.f, 0.f, 0.f, 0.f);
    float4 a1 = make_float4(0.f, 0.f, 0.f, 0.f);

    for (int base = e0; base < e1; base += 256) {
        int m = min(256, e1 - base);
        __syncthreads();
        if (tid < m) se[tid] = g_csr[base + tid];
        __syncthreads();
        #pragma unroll 4
        for (int e = 0; e < m; ++e) {
            int2 sv = se[e];
            float v = __int_as_float(sv.y);
            size_t off = (size_t)sv.x * 128;
            float4 r0 = __ldg((const float4*)(tb0 + off) + q);
            float4 r1 = __ldg((const float4*)(tb1 + off) + q);
            a0.x = fmaf(v, r0.x, a0.x); a0.y = fmaf(v, r0.y, a0.y);
            a0.z = fmaf(v, r0.z, a0.z); a0.w = fmaf(v, r0.w, a0.w);
            a1.x = fmaf(v, r1.x, a1.x); a1.y = fmaf(v, r1.y, a1.y);
            a1.z = fmaf(v, r1.z, a1.z); a1.w = fmaf(v, r1.w, a1.w);
        }
    }
    float di = g_dinv[i];
    size_t soff = (size_t)i * 128;
    float4 s0 = __ldg((const float4*)(tb0 + soff) + q);
    float4 s1 = __ldg((const float4*)(tb1 + soff) + q);
    a0.x = fmaf(di, s0.x, a0.x); a0.y = fmaf(di, s0.y, a0.y);
    a0.z = fmaf(di, s0.z, a0.z); a0.w = fmaf(di, s0.w, a0.w);
    a1.x = fmaf(di, s1.x, a1.x); a1.y = fmaf(di, s1.y, a1.y);
    a1.z = fmaf(di, s1.z, a1.z); a1.w = fmaf(di, s1.w, a1.w);
    float4 bb = __ldg((const float4*)biasc + q);
    float4 o0, o1;
    o0.x = fmaxf(fmaf(di, a0.x, bb.x), 0.f);
    o0.y = fmaxf(fmaf(di, a0.y, bb.y), 0.f);
    o0.z = fmaxf(fmaf(di, a0.z, bb.z), 0.f);
    o0.w = fmaxf(fmaf(di, a0.w, bb.w), 0.f);
    o1.x = fmaxf(fmaf(di, a1.x, bb.x), 0.f);
    o1.y = fmaxf(fmaf(di, a1.y, bb.y), 0.f);
    o1.z = fmaxf(fmaf(di, a1.z, bb.z), 0.f);
    o1.w = fmaxf(fmaf(di, a1.w, bb.w), 0.f);
    __stcs((float4*)(outAll + (size_t)w * BATCH + soff) + q, o0);
    __stcs((float4*)(outAll + (size_t)(w + 8) * BATCH + soff) + q, o1);
    // fused layer-1 scores for both tb
    float4 pv = __ldg((const float4*)p1 + q);
    float sa = o0.x * pv.x + o0.y * pv.y + o0.z * pv.z + o0.w * pv.w;
    float sb = o1.x * pv.x + o1.y * pv.y + o1.z * pv.z + o1.w * pv.w;
    #pragma unroll
    for (int off = 16; off > 0; off >>= 1) {
        sa += __shfl_down_sync(0xffffffffu, sa, off);
        sb += __shfl_down_sync(0xffffffffu, sb, off);
    }
    if (q == 0) {
        float inv = 1.f / g_pnorm[1];
        scAll[w * NNODE + i] = sa * inv;
        scAll[(w + 8) * NNODE + i] = sb * inv;
    }
}

// ---------------- final propagation (2 tb) ----------------
__global__ void __launch_bounds__(64) prop_final_kernel(const float* __restrict__ tmpAll,
                                                        float* __restrict__ dout,
                                                        const float* __restrict__ biasc) {
    __shared__ int2 se[64];
    int i = blockIdx.x;
    int tid = threadIdx.x;
    int b = tid >> 5, q = tid & 31;
    const float* tb = tmpAll + (size_t)b * BATCH;
    int e0 = g_colptr[i], e1 = g_colptr[i + 1];
    float4 acc = make_float4(0.f, 0.f, 0.f, 0.f);

    for (int base = e0; base < e1; base += 64) {
        int m = min(64, e1 - base);
        __syncthreads();
        if (tid < m) se[tid] = g_csr[base + tid];
        __syncthreads();
        #pragma unroll 4
        for (int e = 0; e < m; ++e) {
            int2 sv = se[e];
            float v = __int_as_float(sv.y);
            float4 r = __ldg((const float4*)(tb + (size_t)sv.x * 128) + q);
            acc.x = fmaf(v, r.x, acc.x); acc.y = fmaf(v, r.y, acc.y);
            acc.z = fmaf(v, r.z, acc.z); acc.w = fmaf(v, r.w, acc.w);
        }
    }
    float di = g_dinv[i];
    float4 sv = __ldg((const float4*)(tb + (size_t)i * 128) + q);
    acc.x = fmaf(di, sv.x, acc.x); acc.y = fmaf(di, sv.y, acc.y);
    acc.z = fmaf(di, sv.z, acc.z); acc.w = fmaf(di, sv.w, acc.w);
    float4 bb = __ldg((const float4*)biasc + q);
    float4 o;
    o.x = fmaxf(fmaf(di, acc.x, bb.x), 0.f);
    o.y = fmaxf(fmaf(di, acc.y, bb.y), 0.f);
    o.z = fmaxf(fmaf(di, acc.z, bb.z), 0.f);
    o.w = fmaxf(fmaf(di, acc.w, bb.w), 0.f);
    *((float4*)(dout + (size_t)b * BATCH + (size_t)i * 128) + q) = o;
}

// ---------------- launcher ----------------
extern "C" void kernel_launch(void* const* d_in, const int* in_sizes, int n_in,
                              void* d_out, int out_size) {
    const float* x   = (const float*)d_in[0];
    const void*  ei  = d_in[1];
    const float* ew  = (const float*)d_in[2];
    const float* W0  = (const float*)d_in[3];
    const float* p   = (const float*)d_in[4];
    const float* wih = (const float*)d_in[5];
    const float* whh = (const float*)d_in[6];
    const float* bih = (const float*)d_in[7];
    const float* bhh = (const float*)d_in[8];
    const float* bias = (const float*)d_in[9];
    float* dout = (float*)d_out;
    int E = in_sizes[2];

    cudaFuncSetAttribute(gemm_kernel, cudaFuncAttributeMaxDynamicSharedMemorySize, GEMM_SMEM);

    // pointers to device globals (host side)
    float *pH0A, *pH0B, *pH1A, *pH1B, *pHT0, *pHT1, *pP0, *pP1, *pTmp, *pOut0, *pSc1;
    cudaGetSymbolAddress((void**)&pH0A, g_H0A);
    cudaGetSymbolAddress((void**)&pH0B, g_H0B);
    cudaGetSymbolAddress((void**)&pH1A, g_H1A);
    cudaGetSymbolAddress((void**)&pH1B, g_H1B);
    cudaGetSymbolAddress((void**)&pHT0, g_HT0All);
    cudaGetSymbolAddress((void**)&pHT1, g_HT1);
    cudaGetSymbolAddress((void**)&pP0, g_pooled0);
    cudaGetSymbolAddress((void**)&pP1, g_pooled1All);
    cudaGetSymbolAddress((void**)&pTmp, g_tmpAll);
    cudaGetSymbolAddress((void**)&pOut0, g_out0All);
    cudaGetSymbolAddress((void**)&pSc1, g_scores1All);

    // ---- preprocessing ----
    detect_kernel<<<1, 256>>>((const int*)ei, E);
    zero_kernel<<<(NNODE + 255) / 256, 256>>>();
    norms_kernel<<<1, 64>>>(p);
    deg_kernel<<<(E + 255) / 256, 256>>>(ei, ew, E);
    dinv_kernel<<<(NNODE + 255) / 256, 256>>>();
    scan_kernel<<<1, 256>>>();
    fill_kernel<<<(E + 255) / 256, 256>>>(ei, ew, E);
    hinit_kernel<<<256, 256>>>(W0);
    scores0_kernel<<<(NT * NB * NNODE + 7) / 8, 256>>>(x, p);
    topk_pool_kernel<<<16, 1024>>>(x, 0);

    dim3 gruGrid(16, 8);
    // ---- layer-0 GRU chain (only serial dependency) ----
    for (int t = 0; t < 8; ++t) {
        const float* Hin = (t & 1) ? pH0B : pH0A;
        float* Hout = (t & 1) ? pH0A : pH0B;
        gru_kernel<<<gruGrid, 256>>>(pP0 + (size_t)t * 32768, Hin, Hout,
                                     pHT0 + (size_t)t * NB * 16384, wih, whh, bih, bhh);
    }
    // ---- all 8 layer-0 GEMMs in one launch ----
    gemm_kernel<<<dim3((NNODE + 63) / 64, 2, 8), 256, GEMM_SMEM>>>(
        x, (long)NT * BATCH, (long)BATCH, pHT0, pTmp);
    // ---- all 16 (t,b) propagations in ONE launch ----
    prop16_kernel<<<NNODE, 256>>>(pTmp, pOut0, pSc1, p + 128, bias);
    // ---- all 8 layer-1 top-k+pool in one launch ----
    topk_pool_kernel<<<16, 1024>>>(x, 1);
    // ---- layer-1 GRU chain ----
    for (int t = 0; t < 8; ++t) {
        const float* Hin = (t & 1) ? pH1B : pH1A;
        float* Hout = (t & 1) ? pH1A : pH1B;
        gru_kernel<<<gruGrid, 256>>>(pP1 + (size_t)t * 32768, Hin, Hout,
                                     pHT1, wih + 49152, whh + 49152, bih + 384, bhh + 384);
    }
    // ---- final layer-1 GEMM (t=7) + propagation to output ----
    gemm_kernel<<<dim3((NNODE + 63) / 64, 2, 1), 256, GEMM_SMEM>>>(
        pOut0 + (size_t)14 * BATCH, (long)BATCH, 0L, pHT1, pTmp);
    prop_final_kernel<<<NNODE, 64>>>(pTmp, dout, bias + 128);
}